// round 2
// baseline (speedup 1.0000x reference)
#include <cuda_runtime.h>

#define BB 4
#define NN 4096
#define CC 1024
#define HH 16
#define DH 64
#define RR 266
#define EPSF 1e-3f
#define BHN (BB*HH)   // 64

// ---------------- scratch (device globals; no allocation allowed) ----------
__device__ float g_q [BB*NN*CC];          // 16.7M
__device__ float g_k [BB*NN*CC];
__device__ float g_v [BB*NN*CC];
__device__ float g_qp[(size_t)BHN*NN*RR]; // 69.7M
__device__ float g_kp[(size_t)BHN*NN*RR];
__device__ float g_ksum[BHN*RR];
__device__ float g_dinv[BHN*NN];
__device__ float g_kv[BHN*RR*DH];
__device__ float g_om[BB*NN*CC];

// ---------------- 128x128x16 register-tiled SGEMM (M,N,K % 128/16 == 0) ----
__global__ __launch_bounds__(256) void sgemm128(
    const float* __restrict__ A, const float* __restrict__ B,
    const float* __restrict__ bias, float* __restrict__ C,
    int M, int N, int K)
{
    __shared__ float As[16][132];   // [k][m], padded
    __shared__ float Bs[16][128];   // [k][n]
    const int tid = threadIdx.x;
    const int tx = tid & 15, ty = tid >> 4;
    const int row0 = blockIdx.y * 128, col0 = blockIdx.x * 128;

    float acc[8][8] = {};

    for (int k0 = 0; k0 < K; k0 += 16) {
        #pragma unroll
        for (int t = 0; t < 2; t++) {
            int f = tid + t * 256;               // float4 index in [0,512)
            int arow = f >> 2, ak = (f & 3) * 4;
            float4 va = *(const float4*)&A[(size_t)(row0 + arow) * K + k0 + ak];
            As[ak + 0][arow] = va.x;
            As[ak + 1][arow] = va.y;
            As[ak + 2][arow] = va.z;
            As[ak + 3][arow] = va.w;
            int brow = f >> 5, bc = (f & 31) * 4;
            *(float4*)&Bs[brow][bc] =
                *(const float4*)&B[(size_t)(k0 + brow) * N + col0 + bc];
        }
        __syncthreads();
        #pragma unroll
        for (int k = 0; k < 16; k++) {
            float ar[8], br[8];
            *(float4*)&ar[0] = *(const float4*)&As[k][ty * 8];
            *(float4*)&ar[4] = *(const float4*)&As[k][ty * 8 + 4];
            *(float4*)&br[0] = *(const float4*)&Bs[k][tx * 8];
            *(float4*)&br[4] = *(const float4*)&Bs[k][tx * 8 + 4];
            #pragma unroll
            for (int i = 0; i < 8; i++)
                #pragma unroll
                for (int j = 0; j < 8; j++)
                    acc[i][j] += ar[i] * br[j];
        }
        __syncthreads();
    }

    #pragma unroll
    for (int i = 0; i < 8; i++) {
        int r = row0 + ty * 8 + i;
        #pragma unroll
        for (int j = 0; j < 8; j += 4) {
            int c = col0 + tx * 8 + j;
            float4 o;
            o.x = acc[i][j];     o.y = acc[i][j + 1];
            o.z = acc[i][j + 2]; o.w = acc[i][j + 3];
            if (bias) {
                o.x += bias[c];     o.y += bias[c + 1];
                o.z += bias[c + 2]; o.w += bias[c + 3];
            }
            *(float4*)&C[(size_t)r * N + c] = o;
        }
    }
}

// ---------------- feature map: qp/kp = relu(head @ proj^T) + eps -----------
// grid (ceil(R/64)=5, N/64=64, 2*BHN=128), block 256
__global__ __launch_bounds__(256) void featmap_kernel(const float* __restrict__ proj)
{
    const int z = blockIdx.z;
    const int which = z >> 6;            // 0 -> q, 1 -> k
    const int bh = z & 63;
    const int b = bh >> 4, h = bh & 15;
    const float* __restrict__ src = which ? g_k : g_q;
    float* __restrict__ dst = which ? g_kp : g_qp;
    const int n0 = blockIdx.y * 64;
    const int r0 = blockIdx.x * 64;

    __shared__ float Ast[64][65];   // [d][i]
    __shared__ float Bs[64][65];    // [d][rl]
    const int tid = threadIdx.x;

    #pragma unroll
    for (int t = 0; t < 16; t++) {
        int e = tid + t * 256;
        int i = e >> 6, d = e & 63;
        Ast[d][i] = src[(size_t)(b * NN + n0 + i) * CC + h * 64 + d];
        int rr = r0 + i;
        Bs[d][i] = (rr < RR) ? proj[rr * 64 + d] : 0.0f;
    }
    __syncthreads();

    const int tx = tid & 15, ty = tid >> 4;
    float acc[4][4] = {};
    #pragma unroll 16
    for (int k = 0; k < 64; k++) {
        float a[4], bq[4];
        #pragma unroll
        for (int i = 0; i < 4; i++) a[i] = Ast[k][ty * 4 + i];
        #pragma unroll
        for (int j = 0; j < 4; j++) bq[j] = Bs[k][tx * 4 + j];
        #pragma unroll
        for (int i = 0; i < 4; i++)
            #pragma unroll
            for (int j = 0; j < 4; j++)
                acc[i][j] += a[i] * bq[j];
    }

    #pragma unroll
    for (int i = 0; i < 4; i++) {
        int n = n0 + ty * 4 + i;
        #pragma unroll
        for (int j = 0; j < 4; j++) {
            int r = r0 + tx * 4 + j;
            if (r < RR) {
                float v = acc[i][j];
                v = v > 0.0f ? v : 0.0f;
                dst[((size_t)bh * NN + n) * RR + r] = v + EPSF;
            }
        }
    }
}

// ---------------- k_sum = sum_n kp ------------------------------------------
// grid (BHN, 3, NN/256=16), block 128
__global__ void ksum_kernel()
{
    const int bh = blockIdx.x;
    const int r = blockIdx.y * 128 + threadIdx.x;
    if (r >= RR) return;
    const int n0 = blockIdx.z * 256;
    const float* __restrict__ base = g_kp + (size_t)bh * NN * RR;
    float s0 = 0.f, s1 = 0.f, s2 = 0.f, s3 = 0.f;
    #pragma unroll 4
    for (int n = n0; n < n0 + 256; n += 4) {
        s0 += base[(size_t)(n + 0) * RR + r];
        s1 += base[(size_t)(n + 1) * RR + r];
        s2 += base[(size_t)(n + 2) * RR + r];
        s3 += base[(size_t)(n + 3) * RR + r];
    }
    atomicAdd(&g_ksum[bh * RR + r], (s0 + s1) + (s2 + s3));
}

// ---------------- d_inv = 1 / (qp . k_sum) ----------------------------------
// one warp per (bh, n); grid 32768 blocks x 256 threads (8 warps)
__global__ void dinv_kernel()
{
    const int gw = (blockIdx.x * blockDim.x + threadIdx.x) >> 5;
    const int lane = threadIdx.x & 31;
    const int bh = gw >> 12;      // / 4096
    const int n = gw & 4095;
    const float* __restrict__ qrow = g_qp + ((size_t)bh * NN + n) * RR;
    const float* __restrict__ ks = g_ksum + bh * RR;
    float s = 0.f;
    for (int r = lane; r < RR; r += 32) s += qrow[r] * ks[r];
    #pragma unroll
    for (int o = 16; o; o >>= 1) s += __shfl_xor_sync(0xffffffffu, s, o);
    if (lane == 0) g_dinv[(size_t)bh * NN + n] = 1.0f / s;
}

// ---------------- kv = kp^T @ v per head (R x HC) ----------------------------
// grid (BHN, ceil(R/64)=5), block 256; thread owns 2 r-rows x 8 cols
__global__ __launch_bounds__(256) void kv_kernel()
{
    const int bh = blockIdx.x;
    const int b = bh >> 4, h = bh & 15;
    const int r0 = blockIdx.y * 64;

    __shared__ float kps[64][65];   // [nn][rl]
    __shared__ float vs[64][64];    // [nn][c]
    const int tid = threadIdx.x;
    const int rlo = tid >> 3;            // 0..31
    const int c0 = (tid & 7) * 8;

    float acc0[8] = {}, acc1[8] = {};
    const float* __restrict__ kpb = g_kp + (size_t)bh * NN * RR;
    const float* __restrict__ vb  = g_v + (size_t)b * NN * CC + h * 64;

    for (int n0 = 0; n0 < NN; n0 += 64) {
        #pragma unroll
        for (int t = 0; t < 16; t++) {
            int e = tid + t * 256;
            int nn = e >> 6, rl = e & 63;
            int rr = r0 + rl;
            kps[nn][rl] = (rr < RR) ? kpb[(size_t)(n0 + nn) * RR + rr] : 0.0f;
        }
        #pragma unroll
        for (int t = 0; t < 16; t++) {
            int e = tid + t * 256;
            int nn = e >> 6, c = e & 63;
            vs[nn][c] = vb[(size_t)(n0 + nn) * CC + c];
        }
        __syncthreads();
        #pragma unroll 8
        for (int nn = 0; nn < 64; nn++) {
            float a0 = kps[nn][rlo];
            float a1 = kps[nn][rlo + 32];
            float4 v0 = *(const float4*)&vs[nn][c0];
            float4 v1 = *(const float4*)&vs[nn][c0 + 4];
            acc0[0] += a0 * v0.x; acc0[1] += a0 * v0.y;
            acc0[2] += a0 * v0.z; acc0[3] += a0 * v0.w;
            acc0[4] += a0 * v1.x; acc0[5] += a0 * v1.y;
            acc0[6] += a0 * v1.z; acc0[7] += a0 * v1.w;
            acc1[0] += a1 * v0.x; acc1[1] += a1 * v0.y;
            acc1[2] += a1 * v0.z; acc1[3] += a1 * v0.w;
            acc1[4] += a1 * v1.x; acc1[5] += a1 * v1.y;
            acc1[6] += a1 * v1.z; acc1[7] += a1 * v1.w;
        }
        __syncthreads();
    }

    int rr0 = r0 + rlo, rr1 = rr0 + 32;
    if (rr0 < RR) {
        #pragma unroll
        for (int j = 0; j < 8; j++)
            g_kv[((size_t)bh * RR + rr0) * 64 + c0 + j] = acc0[j];
    }
    if (rr1 < RR) {
        #pragma unroll
        for (int j = 0; j < 8; j++)
            g_kv[((size_t)bh * RR + rr1) * 64 + c0 + j] = acc1[j];
    }
}

// ---------------- qkv = qp @ kv, scaled by d_inv, write merged layout -------
// grid (BHN, NN/64=64), block 256
__global__ __launch_bounds__(256) void qkv_kernel()
{
    const int bh = blockIdx.x;
    const int b = bh >> 4, h = bh & 15;
    const int n0 = blockIdx.y * 64;

    __shared__ float qpsT[64][65];  // [kk][i]
    __shared__ float kvs[64][64];   // [kk][c]
    const int tid = threadIdx.x;
    const int tx = tid & 15, ty = tid >> 4;

    float acc[4][4] = {};
    const float* __restrict__ qpb = g_qp + (size_t)bh * NN * RR;
    const float* __restrict__ kvb = g_kv + (size_t)bh * RR * 64;

    for (int k0 = 0; k0 < RR; k0 += 64) {
        #pragma unroll
        for (int t = 0; t < 16; t++) {
            int e = tid + t * 256;
            int i = e >> 6, kk = e & 63;
            int kr = k0 + kk;
            qpsT[kk][i] = (kr < RR) ? qpb[(size_t)(n0 + i) * RR + kr] : 0.0f;
        }
        #pragma unroll
        for (int t = 0; t < 16; t++) {
            int e = tid + t * 256;
            int kk = e >> 6, c = e & 63;
            int kr = k0 + kk;
            kvs[kk][c] = (kr < RR) ? kvb[(size_t)kr * 64 + c] : 0.0f;
        }
        __syncthreads();
        #pragma unroll 16
        for (int k = 0; k < 64; k++) {
            float a[4], bq[4];
            #pragma unroll
            for (int i = 0; i < 4; i++) a[i] = qpsT[k][ty * 4 + i];
            #pragma unroll
            for (int j = 0; j < 4; j++) bq[j] = kvs[k][tx * 4 + j];
            #pragma unroll
            for (int i = 0; i < 4; i++)
                #pragma unroll
                for (int j = 0; j < 4; j++)
                    acc[i][j] += a[i] * bq[j];
        }
        __syncthreads();
    }

    #pragma unroll
    for (int i = 0; i < 4; i++) {
        int n = n0 + ty * 4 + i;
        float di = g_dinv[(size_t)bh * NN + n];
        #pragma unroll
        for (int j = 0; j < 4; j++) {
            int c = tx * 4 + j;
            g_om[(size_t)(b * NN + n) * CC + h * 64 + c] = acc[i][j] * di;
        }
    }
}

// ---------------- launch -----------------------------------------------------
extern "C" void kernel_launch(void* const* d_in, const int* in_sizes, int n_in,
                              void* d_out, int out_size)
{
    const float* x    = (const float*)d_in[0];
    const float* Wq   = (const float*)d_in[1];
    const float* Wk   = (const float*)d_in[2];
    const float* Wv   = (const float*)d_in[3];
    const float* Wo   = (const float*)d_in[4];
    const float* bo   = (const float*)d_in[5];
    const float* proj = (const float*)d_in[6];

    float *q, *k, *v, *om, *ksum;
    cudaGetSymbolAddress((void**)&q,    g_q);
    cudaGetSymbolAddress((void**)&k,    g_k);
    cudaGetSymbolAddress((void**)&v,    g_v);
    cudaGetSymbolAddress((void**)&om,   g_om);
    cudaGetSymbolAddress((void**)&ksum, g_ksum);

    const int M = BB * NN;   // 16384

    dim3 gBig(CC / 128, M / 128);   // (8, 128)
    sgemm128<<<gBig, 256>>>(x, Wq, nullptr, q, M, CC, CC);
    sgemm128<<<gBig, 256>>>(x, Wk, nullptr, k, M, CC, CC);
    sgemm128<<<gBig, 256>>>(x, Wv, nullptr, v, M, CC, CC);

    featmap_kernel<<<dim3(5, NN / 64, 2 * BHN), 256>>>(proj);

    cudaMemsetAsync(ksum, 0, BHN * RR * sizeof(float));
    ksum_kernel<<<dim3(BHN, 3, NN / 256), 128>>>();

    dinv_kernel<<<(BHN * NN) / 8, 256>>>();

    kv_kernel<<<dim3(BHN, 5), 256>>>();

    qkv_kernel<<<dim3(BHN, NN / 64), 256>>>();

    sgemm128<<<gBig, 256>>>(om, Wo, bo, (float*)d_out, M, CC, CC);
}

// round 4
// speedup vs baseline: 1.5107x; 1.5107x over previous
#include <cuda_runtime.h>
#include <cuda_bf16.h>
#include <cstdint>

#define BB 4
#define NN 4096
#define CC 1024
#define HH 16
#define DH 64
#define RR 266
#define EPSF 1e-3f
#define BHN (BB*HH)   // 64
#define GM (BB*NN)    // 16384
#define GK 1024
#define GN 1024
#define KC 32
#define NCH (GK/KC)        // 32 chunks
#define MAT_BYTES (128*80) // 128 rows x 80B (40 halves, padded)
#define STAGE_BYTES (4*MAT_BYTES)  // 40960
#define SMEM_DYN (2*STAGE_BYTES)   // 81920

// ---------------- scratch (device globals; no allocation allowed) ----------
__device__ float g_q [BB*NN*CC];
__device__ float g_k [BB*NN*CC];
__device__ float g_v [BB*NN*CC];
__device__ float g_qp[(size_t)BHN*NN*RR];
__device__ float g_kp[(size_t)BHN*NN*RR];
__device__ float g_ksum[BHN*RR];
__device__ float g_dinv[BHN*NN];
__device__ float g_kv[BHN*RR*DH];
__device__ float g_om[BB*NN*CC];
// bf16 split buffers
__device__ __nv_bfloat16 g_xh[(size_t)GM*GK];
__device__ __nv_bfloat16 g_xl[(size_t)GM*GK];
__device__ __nv_bfloat16 g_omh[(size_t)GM*GK];
__device__ __nv_bfloat16 g_oml[(size_t)GM*GK];
__device__ __nv_bfloat16 g_wth[(size_t)4*GN*GK];   // transposed [N][K], q,k,v,o
__device__ __nv_bfloat16 g_wtl[(size_t)4*GN*GK];

// ---------------- helpers ----------------------------------------------------
__device__ __forceinline__ uint32_t smem_u32(const void* p) {
    uint32_t a;
    asm("{ .reg .u64 t; cvta.to.shared.u64 t, %1; cvt.u32.u64 %0, t; }"
        : "=r"(a) : "l"(p));
    return a;
}
__device__ __forceinline__ void ldsm4(uint32_t* r, uint32_t addr) {
    asm volatile("ldmatrix.sync.aligned.m8n8.x4.shared.b16 {%0,%1,%2,%3}, [%4];"
        : "=r"(r[0]), "=r"(r[1]), "=r"(r[2]), "=r"(r[3]) : "r"(addr));
}
__device__ __forceinline__ void mma16816(float* d, const uint32_t* a, const uint32_t* b) {
    asm volatile(
        "mma.sync.aligned.m16n8k16.row.col.f32.bf16.bf16.f32 "
        "{%0,%1,%2,%3}, {%4,%5,%6,%7}, {%8,%9}, {%0,%1,%2,%3};"
        : "+f"(d[0]), "+f"(d[1]), "+f"(d[2]), "+f"(d[3])
        : "r"(a[0]), "r"(a[1]), "r"(a[2]), "r"(a[3]), "r"(b[0]), "r"(b[1]));
}

// ---------------- HMMA split-bf16 GEMM: C[GM,GN] = A @ Bt^T (+bias) ---------
// grid (GN/128, GM/128), 256 threads, dyn smem SMEM_DYN
__global__ __launch_bounds__(256) void gemm_hmma(
    const __nv_bfloat16* __restrict__ Ah, const __nv_bfloat16* __restrict__ Al,
    const __nv_bfloat16* __restrict__ Bh, const __nv_bfloat16* __restrict__ Bl,
    const float* __restrict__ bias, float* __restrict__ C)
{
    extern __shared__ char smem[];
    const int tid = threadIdx.x;
    const int wid = tid >> 5, lane = tid & 31;
    const int m0 = blockIdx.y * 128, n0 = blockIdx.x * 128;
    const int wr = wid >> 2, wc = wid & 3;   // warp 2x4 grid; warp tile 64x32

    const __nv_bfloat16* gsrc0 = Ah + (size_t)m0 * GK;
    const __nv_bfloat16* gsrc1 = Al + (size_t)m0 * GK;
    const __nv_bfloat16* gsrc2 = Bh + (size_t)n0 * GK;
    const __nv_bfloat16* gsrc3 = Bl + (size_t)n0 * GK;

    float acc[4][4][4] = {};

    // ---- async stage loader: 4 matrices x 128 rows x 64B -> padded 80B rows
    auto load_stage = [&](int c, int st) {
        const int k0 = c * KC;
        char* dstb = smem + st * STAGE_BYTES;
        #pragma unroll
        for (int i = 0; i < 8; i++) {
            int idx = tid + i * 256;            // [0,2048)
            int mat = idx >> 9;
            int row = (idx >> 2) & 127;
            int c16 = idx & 3;
            uint32_t dst = smem_u32(dstb + mat * MAT_BYTES + row * 80 + c16 * 16);
            const __nv_bfloat16* g =
                (mat == 0) ? gsrc0 : (mat == 1) ? gsrc1 : (mat == 2) ? gsrc2 : gsrc3;
            const void* src = g + (size_t)row * GK + k0 + c16 * 8;
            asm volatile("cp.async.cg.shared.global [%0], [%1], 16;"
                         :: "r"(dst), "l"(src));
        }
        asm volatile("cp.async.commit_group;" ::: "memory");
    };

    load_stage(0, 0);

    for (int c = 0; c < NCH; c++) {
        if (c + 1 < NCH) {
            load_stage(c + 1, (c + 1) & 1);
            asm volatile("cp.async.wait_group 1;" ::: "memory");
        } else {
            asm volatile("cp.async.wait_group 0;" ::: "memory");
        }
        __syncthreads();

        const int st = c & 1;
        const uint32_t aH = smem_u32(smem + st * STAGE_BYTES);
        const uint32_t aL = aH + MAT_BYTES;
        const uint32_t bH = aH + 2 * MAT_BYTES;
        const uint32_t bL = aH + 3 * MAT_BYTES;

        #pragma unroll
        for (int kt = 0; kt < 2; kt++) {
            uint32_t ah[4][4], al[4][4], bh[2][4], bl[2][4];
            // A fragments (m16k16): lane -> row (lane&15), k-half (lane>>4)
            const int arow = wr * 64 + (lane & 15);
            const uint32_t akoff = (uint32_t)(kt * 16 + (lane >> 4) * 8) * 2;
            #pragma unroll
            for (int mt = 0; mt < 4; mt++) {
                ldsm4(ah[mt], aH + (uint32_t)(arow + mt * 16) * 80 + akoff);
                ldsm4(al[mt], aL + (uint32_t)(arow + mt * 16) * 80 + akoff);
            }
            // B fragments (two n8k16 tiles per ldsm4)
            const int g = lane >> 3;
            const int brow = wc * 32 + (lane & 7) + (g >> 1) * 8;
            const uint32_t bkoff = (uint32_t)(kt * 16 + (g & 1) * 8) * 2;
            #pragma unroll
            for (int nt2 = 0; nt2 < 2; nt2++) {
                ldsm4(bh[nt2], bH + (uint32_t)(brow + nt2 * 16) * 80 + bkoff);
                ldsm4(bl[nt2], bL + (uint32_t)(brow + nt2 * 16) * 80 + bkoff);
            }
            #pragma unroll
            for (int mt = 0; mt < 4; mt++)
                #pragma unroll
                for (int nt = 0; nt < 4; nt++) {
                    const uint32_t* bhp = &bh[nt >> 1][(nt & 1) * 2];
                    const uint32_t* blp = &bl[nt >> 1][(nt & 1) * 2];
                    mma16816(acc[mt][nt], ah[mt], bhp);
                    mma16816(acc[mt][nt], ah[mt], blp);
                    mma16816(acc[mt][nt], al[mt], bhp);
                }
        }
        __syncthreads();
    }

    // ---- epilogue: write fp32 (+bias)
    const int qr = lane >> 2, qc = lane & 3;
    #pragma unroll
    for (int mt = 0; mt < 4; mt++) {
        #pragma unroll
        for (int nt = 0; nt < 4; nt++) {
            int row = m0 + wr * 64 + mt * 16 + qr;
            int col = n0 + wc * 32 + nt * 8 + qc * 2;
            float bx = 0.f, by = 0.f;
            if (bias) { bx = bias[col]; by = bias[col + 1]; }
            float2 v0 = {acc[mt][nt][0] + bx, acc[mt][nt][1] + by};
            float2 v1 = {acc[mt][nt][2] + bx, acc[mt][nt][3] + by};
            *(float2*)&C[(size_t)row * GN + col] = v0;
            *(float2*)&C[(size_t)(row + 8) * GN + col] = v1;
        }
    }
}

// ---------------- fp32 -> bf16 hi/lo split ----------------------------------
__global__ __launch_bounds__(256) void split_kernel(
    const float* __restrict__ in, __nv_bfloat16* __restrict__ hi,
    __nv_bfloat16* __restrict__ lo, int n4)
{
    int i = blockIdx.x * blockDim.x + threadIdx.x;
    if (i >= n4) return;
    float4 v = ((const float4*)in)[i];
    float vv[4] = {v.x, v.y, v.z, v.w};
    __nv_bfloat16 h[4], l[4];
    #pragma unroll
    for (int j = 0; j < 4; j++) {
        h[j] = __float2bfloat16(vv[j]);
        l[j] = __float2bfloat16(vv[j] - __bfloat162float(h[j]));
    }
    ((__nv_bfloat162*)hi)[2*i+0] = __nv_bfloat162{h[0], h[1]};
    ((__nv_bfloat162*)hi)[2*i+1] = __nv_bfloat162{h[2], h[3]};
    ((__nv_bfloat162*)lo)[2*i+0] = __nv_bfloat162{l[0], l[1]};
    ((__nv_bfloat162*)lo)[2*i+1] = __nv_bfloat162{l[2], l[3]};
}

// ---------------- transpose + split weights: W[K][N] -> Wt hi/lo [N][K] -----
__global__ void wsplit_t(const float* __restrict__ W,
                         __nv_bfloat16* __restrict__ th,
                         __nv_bfloat16* __restrict__ tl)
{
    __shared__ float t[32][33];
    const int k0 = blockIdx.y * 32, n0 = blockIdx.x * 32;
    for (int i = threadIdx.y; i < 32; i += 8)
        t[i][threadIdx.x] = W[(size_t)(k0 + i) * GN + n0 + threadIdx.x];
    __syncthreads();
    for (int i = threadIdx.y; i < 32; i += 8) {
        float v = t[threadIdx.x][i];
        __nv_bfloat16 h = __float2bfloat16(v);
        __nv_bfloat16 l = __float2bfloat16(v - __bfloat162float(h));
        size_t o = (size_t)(n0 + i) * GK + k0 + threadIdx.x;
        th[o] = h;
        tl[o] = l;
    }
}

// ---------------- feature map: qp/kp = relu(head @ proj^T) + eps -----------
__global__ __launch_bounds__(256) void featmap_kernel(const float* __restrict__ proj)
{
    const int z = blockIdx.z;
    const int which = z >> 6;
    const int bh = z & 63;
    const int b = bh >> 4, h = bh & 15;
    const float* __restrict__ src = which ? g_k : g_q;
    float* __restrict__ dst = which ? g_kp : g_qp;
    const int n0 = blockIdx.y * 64;
    const int r0 = blockIdx.x * 64;

    __shared__ float Ast[64][65];
    __shared__ float Bs[64][65];
    const int tid = threadIdx.x;

    #pragma unroll
    for (int t = 0; t < 16; t++) {
        int e = tid + t * 256;
        int i = e >> 6, d = e & 63;
        Ast[d][i] = src[(size_t)(b * NN + n0 + i) * CC + h * 64 + d];
        int rr = r0 + i;
        Bs[d][i] = (rr < RR) ? proj[rr * 64 + d] : 0.0f;
    }
    __syncthreads();

    const int tx = tid & 15, ty = tid >> 4;
    float acc[4][4] = {};
    #pragma unroll 16
    for (int k = 0; k < 64; k++) {
        float a[4], bq[4];
        #pragma unroll
        for (int i = 0; i < 4; i++) a[i] = Ast[k][ty * 4 + i];
        #pragma unroll
        for (int j = 0; j < 4; j++) bq[j] = Bs[k][tx * 4 + j];
        #pragma unroll
        for (int i = 0; i < 4; i++)
            #pragma unroll
            for (int j = 0; j < 4; j++)
                acc[i][j] += a[i] * bq[j];
    }

    #pragma unroll
    for (int i = 0; i < 4; i++) {
        int n = n0 + ty * 4 + i;
        #pragma unroll
        for (int j = 0; j < 4; j++) {
            int r = r0 + tx * 4 + j;
            if (r < RR) {
                float v = acc[i][j];
                v = v > 0.0f ? v : 0.0f;
                dst[((size_t)bh * NN + n) * RR + r] = v + EPSF;
            }
        }
    }
}

// ---------------- k_sum = sum_n kp ------------------------------------------
__global__ void ksum_kernel()
{
    const int bh = blockIdx.x;
    const int r = blockIdx.y * 128 + threadIdx.x;
    if (r >= RR) return;
    const int n0 = blockIdx.z * 256;
    const float* __restrict__ base = g_kp + (size_t)bh * NN * RR;
    float s0 = 0.f, s1 = 0.f, s2 = 0.f, s3 = 0.f;
    #pragma unroll 4
    for (int n = n0; n < n0 + 256; n += 4) {
        s0 += base[(size_t)(n + 0) * RR + r];
        s1 += base[(size_t)(n + 1) * RR + r];
        s2 += base[(size_t)(n + 2) * RR + r];
        s3 += base[(size_t)(n + 3) * RR + r];
    }
    atomicAdd(&g_ksum[bh * RR + r], (s0 + s1) + (s2 + s3));
}

// ---------------- d_inv = 1 / (qp . k_sum) ----------------------------------
__global__ void dinv_kernel()
{
    const int gw = (blockIdx.x * blockDim.x + threadIdx.x) >> 5;
    const int lane = threadIdx.x & 31;
    const int bh = gw >> 12;
    const int n = gw & 4095;
    const float* __restrict__ qrow = g_qp + ((size_t)bh * NN + n) * RR;
    const float* __restrict__ ks = g_ksum + bh * RR;
    float s = 0.f;
    for (int r = lane; r < RR; r += 32) s += qrow[r] * ks[r];
    #pragma unroll
    for (int o = 16; o; o >>= 1) s += __shfl_xor_sync(0xffffffffu, s, o);
    if (lane == 0) g_dinv[(size_t)bh * NN + n] = 1.0f / s;
}

// ---------------- kv = kp^T @ v per head (R x HC) ----------------------------
__global__ __launch_bounds__(256) void kv_kernel()
{
    const int bh = blockIdx.x;
    const int b = bh >> 4, h = bh & 15;
    const int r0 = blockIdx.y * 64;

    __shared__ float kps[64][65];
    __shared__ float vs[64][64];
    const int tid = threadIdx.x;
    const int rlo = tid >> 3;
    const int c0 = (tid & 7) * 8;

    float acc0[8] = {}, acc1[8] = {};
    const float* __restrict__ kpb = g_kp + (size_t)bh * NN * RR;
    const float* __restrict__ vb  = g_v + (size_t)b * NN * CC + h * 64;

    for (int n0 = 0; n0 < NN; n0 += 64) {
        #pragma unroll
        for (int t = 0; t < 16; t++) {
            int e = tid + t * 256;
            int nn = e >> 6, rl = e & 63;
            int rr = r0 + rl;
            kps[nn][rl] = (rr < RR) ? kpb[(size_t)(n0 + nn) * RR + rr] : 0.0f;
        }
        #pragma unroll
        for (int t = 0; t < 16; t++) {
            int e = tid + t * 256;
            int nn = e >> 6, c = e & 63;
            vs[nn][c] = vb[(size_t)(n0 + nn) * CC + c];
        }
        __syncthreads();
        #pragma unroll 8
        for (int nn = 0; nn < 64; nn++) {
            float a0 = kps[nn][rlo];
            float a1 = kps[nn][rlo + 32];
            float4 v0 = *(const float4*)&vs[nn][c0];
            float4 v1 = *(const float4*)&vs[nn][c0 + 4];
            acc0[0] += a0 * v0.x; acc0[1] += a0 * v0.y;
            acc0[2] += a0 * v0.z; acc0[3] += a0 * v0.w;
            acc0[4] += a0 * v1.x; acc0[5] += a0 * v1.y;
            acc0[6] += a0 * v1.z; acc0[7] += a0 * v1.w;
            acc1[0] += a1 * v0.x; acc1[1] += a1 * v0.y;
            acc1[2] += a1 * v0.z; acc1[3] += a1 * v0.w;
            acc1[4] += a1 * v1.x; acc1[5] += a1 * v1.y;
            acc1[6] += a1 * v1.z; acc1[7] += a1 * v1.w;
        }
        __syncthreads();
    }

    int rr0 = r0 + rlo, rr1 = rr0 + 32;
    if (rr0 < RR) {
        #pragma unroll
        for (int j = 0; j < 8; j++)
            g_kv[((size_t)bh * RR + rr0) * 64 + c0 + j] = acc0[j];
    }
    if (rr1 < RR) {
        #pragma unroll
        for (int j = 0; j < 8; j++)
            g_kv[((size_t)bh * RR + rr1) * 64 + c0 + j] = acc1[j];
    }
}

// ---------------- qkv = qp @ kv, scaled by d_inv -----------------------------
__global__ __launch_bounds__(256) void qkv_kernel()
{
    const int bh = blockIdx.x;
    const int b = bh >> 4, h = bh & 15;
    const int n0 = blockIdx.y * 64;

    __shared__ float qpsT[64][65];
    __shared__ float kvs[64][64];
    const int tid = threadIdx.x;
    const int tx = tid & 15, ty = tid >> 4;

    float acc[4][4] = {};
    const float* __restrict__ qpb = g_qp + (size_t)bh * NN * RR;
    const float* __restrict__ kvb = g_kv + (size_t)bh * RR * 64;

    for (int k0 = 0; k0 < RR; k0 += 64) {
        #pragma unroll
        for (int t = 0; t < 16; t++) {
            int e = tid + t * 256;
            int i = e >> 6, kk = e & 63;
            int kr = k0 + kk;
            qpsT[kk][i] = (kr < RR) ? qpb[(size_t)(n0 + i) * RR + kr] : 0.0f;
        }
        #pragma unroll
        for (int t = 0; t < 16; t++) {
            int e = tid + t * 256;
            int kk = e >> 6, c = e & 63;
            int kr = k0 + kk;
            kvs[kk][c] = (kr < RR) ? kvb[(size_t)kr * 64 + c] : 0.0f;
        }
        __syncthreads();
        #pragma unroll 16
        for (int k = 0; k < 64; k++) {
            float a[4], bq[4];
            #pragma unroll
            for (int i = 0; i < 4; i++) a[i] = qpsT[k][ty * 4 + i];
            #pragma unroll
            for (int j = 0; j < 4; j++) bq[j] = kvs[k][tx * 4 + j];
            #pragma unroll
            for (int i = 0; i < 4; i++)
                #pragma unroll
                for (int j = 0; j < 4; j++)
                    acc[i][j] += a[i] * bq[j];
        }
        __syncthreads();
    }

    #pragma unroll
    for (int i = 0; i < 4; i++) {
        int n = n0 + ty * 4 + i;
        float di = g_dinv[(size_t)bh * NN + n];
        #pragma unroll
        for (int j = 0; j < 4; j++) {
            int c = tx * 4 + j;
            g_om[(size_t)(b * NN + n) * CC + h * 64 + c] = acc[i][j] * di;
        }
    }
}

// ---------------- launch -----------------------------------------------------
extern "C" void kernel_launch(void* const* d_in, const int* in_sizes, int n_in,
                              void* d_out, int out_size)
{
    const float* x    = (const float*)d_in[0];
    const float* Wq   = (const float*)d_in[1];
    const float* Wk   = (const float*)d_in[2];
    const float* Wv   = (const float*)d_in[3];
    const float* Wo   = (const float*)d_in[4];
    const float* bo   = (const float*)d_in[5];
    const float* proj = (const float*)d_in[6];

    float *q, *k, *v, *om, *ksum;
    __nv_bfloat16 *xh, *xl, *omh, *oml, *wth, *wtl;
    cudaGetSymbolAddress((void**)&q,    g_q);
    cudaGetSymbolAddress((void**)&k,    g_k);
    cudaGetSymbolAddress((void**)&v,    g_v);
    cudaGetSymbolAddress((void**)&om,   g_om);
    cudaGetSymbolAddress((void**)&ksum, g_ksum);
    cudaGetSymbolAddress((void**)&xh,   g_xh);
    cudaGetSymbolAddress((void**)&xl,   g_xl);
    cudaGetSymbolAddress((void**)&omh,  g_omh);
    cudaGetSymbolAddress((void**)&oml,  g_oml);
    cudaGetSymbolAddress((void**)&wth,  g_wth);
    cudaGetSymbolAddress((void**)&wtl,  g_wtl);

    cudaFuncSetAttribute(gemm_hmma,
                         cudaFuncAttributeMaxDynamicSharedMemorySize, SMEM_DYN);

    const int n4 = GM * GK / 4;

    split_kernel<<<(n4 + 255) / 256, 256>>>(x, xh, xl, n4);
    wsplit_t<<<dim3(32, 32), dim3(32, 8)>>>(Wq, wth + 0 * (size_t)GN * GK, wtl + 0 * (size_t)GN * GK);
    wsplit_t<<<dim3(32, 32), dim3(32, 8)>>>(Wk, wth + 1 * (size_t)GN * GK, wtl + 1 * (size_t)GN * GK);
    wsplit_t<<<dim3(32, 32), dim3(32, 8)>>>(Wv, wth + 2 * (size_t)GN * GK, wtl + 2 * (size_t)GN * GK);
    wsplit_t<<<dim3(32, 32), dim3(32, 8)>>>(Wo, wth + 3 * (size_t)GN * GK, wtl + 3 * (size_t)GN * GK);

    dim3 gG(GN / 128, GM / 128);   // (8, 128)
    gemm_hmma<<<gG, 256, SMEM_DYN>>>(xh, xl, wth + 0 * (size_t)GN * GK, wtl + 0 * (size_t)GN * GK, nullptr, q);
    gemm_hmma<<<gG, 256, SMEM_DYN>>>(xh, xl, wth + 1 * (size_t)GN * GK, wtl + 1 * (size_t)GN * GK, nullptr, k);
    gemm_hmma<<<gG, 256, SMEM_DYN>>>(xh, xl, wth + 2 * (size_t)GN * GK, wtl + 2 * (size_t)GN * GK, nullptr, v);

    featmap_kernel<<<dim3(5, NN / 64, 2 * BHN), 256>>>(proj);

    cudaMemsetAsync(ksum, 0, BHN * RR * sizeof(float));
    ksum_kernel<<<dim3(BHN, 3, NN / 256), 128>>>();

    dinv_kernel<<<(BHN * NN) / 8, 256>>>();

    kv_kernel<<<dim3(BHN, 5), 256>>>();

    qkv_kernel<<<dim3(BHN, NN / 64), 256>>>();

    split_kernel<<<(n4 + 255) / 256, 256>>>(om, omh, oml, n4);
    gemm_hmma<<<gG, 256, SMEM_DYN>>>(omh, oml, wth + 3 * (size_t)GN * GK, wtl + 3 * (size_t)GN * GK, bo, (float*)d_out);
}

// round 5
// speedup vs baseline: 1.7519x; 1.1597x over previous
#include <cuda_runtime.h>
#include <cuda_bf16.h>
#include <cstdint>

#define BB 4
#define NN 4096
#define CC 1024
#define HH 16
#define DH 64
#define RR 266
#define RP 288
#define EPSF 1e-3f
#define BHN (BB*HH)   // 64
#define GM (BB*NN)    // 16384
#define GK 1024
#define GN 1024
#define KC 32
#define NCH (GK/KC)        // 32 chunks
#define MAT_BYTES (128*80) // 128 rows x 80B
#define STAGE_BYTES (4*MAT_BYTES)  // 40960
#define SMEM_DYN (2*STAGE_BYTES)   // 81920
// featmap smem
#define FM_SMEM (2*128*144 + 2*64*144)   // 55296
// qkv smem
#define QKV_STAGE (2*128*80 + 2*64*80)   // 30720
#define QKV_SMEM (2*QKV_STAGE)           // 61440

// ---------------- scratch (device globals; no allocation allowed) ----------
__device__ float g_v [GM*GK];
__device__ float g_ksum[BHN*RP];
__device__ float g_dinv[BHN*NN];
__device__ __nv_bfloat16 g_xh[(size_t)GM*GK];
__device__ __nv_bfloat16 g_xl[(size_t)GM*GK];
__device__ __nv_bfloat16 g_qh[(size_t)GM*GK];
__device__ __nv_bfloat16 g_ql[(size_t)GM*GK];
__device__ __nv_bfloat16 g_kh[(size_t)GM*GK];
__device__ __nv_bfloat16 g_kl[(size_t)GM*GK];
__device__ __nv_bfloat16 g_omh[(size_t)GM*GK];
__device__ __nv_bfloat16 g_oml[(size_t)GM*GK];
__device__ __nv_bfloat16 g_wth[(size_t)4*GN*GK];
__device__ __nv_bfloat16 g_wtl[(size_t)4*GN*GK];
__device__ __nv_bfloat16 g_projh[320*64];
__device__ __nv_bfloat16 g_projl[320*64];
__device__ __nv_bfloat16 g_qph[(size_t)BHN*NN*RP];
__device__ __nv_bfloat16 g_qpl[(size_t)BHN*NN*RP];
__device__ __nv_bfloat16 g_kph[(size_t)BHN*NN*RP];
__device__ __nv_bfloat16 g_kpl[(size_t)BHN*NN*RP];
__device__ __nv_bfloat16 g_kvTh[BHN*64*RP];
__device__ __nv_bfloat16 g_kvTl[BHN*64*RP];

// ---------------- helpers ----------------------------------------------------
__device__ __forceinline__ uint32_t smem_u32(const void* p) {
    uint32_t a;
    asm("{ .reg .u64 t; cvta.to.shared.u64 t, %1; cvt.u32.u64 %0, t; }"
        : "=r"(a) : "l"(p));
    return a;
}
__device__ __forceinline__ void cpa16(uint32_t dst, const void* src) {
    asm volatile("cp.async.cg.shared.global [%0], [%1], 16;" :: "r"(dst), "l"(src));
}
__device__ __forceinline__ void ldsm4(uint32_t* r, uint32_t addr) {
    asm volatile("ldmatrix.sync.aligned.m8n8.x4.shared.b16 {%0,%1,%2,%3}, [%4];"
        : "=r"(r[0]), "=r"(r[1]), "=r"(r[2]), "=r"(r[3]) : "r"(addr));
}
__device__ __forceinline__ void mma16816(float* d, const uint32_t* a, const uint32_t* b) {
    asm volatile(
        "mma.sync.aligned.m16n8k16.row.col.f32.bf16.bf16.f32 "
        "{%0,%1,%2,%3}, {%4,%5,%6,%7}, {%8,%9}, {%0,%1,%2,%3};"
        : "+f"(d[0]), "+f"(d[1]), "+f"(d[2]), "+f"(d[3])
        : "r"(a[0]), "r"(a[1]), "r"(a[2]), "r"(a[3]), "r"(b[0]), "r"(b[1]));
}
__device__ __forceinline__ void split2(float v, __nv_bfloat16& h, __nv_bfloat16& l) {
    h = __float2bfloat16(v);
    l = __float2bfloat16(v - __bfloat162float(h));
}

// ---------------- HMMA split-bf16 GEMM: C = A @ Bt^T (+bias) ---------------
// grid (GN/128, GM/128), 256 threads. Output fp32 (Cf) or bf16 h/l (Ch/Cl).
__global__ __launch_bounds__(256) void gemm_hmma(
    const __nv_bfloat16* __restrict__ Ah, const __nv_bfloat16* __restrict__ Al,
    const __nv_bfloat16* __restrict__ Bh, const __nv_bfloat16* __restrict__ Bl,
    const float* __restrict__ bias, float* __restrict__ Cf,
    __nv_bfloat16* __restrict__ Ch, __nv_bfloat16* __restrict__ Cl)
{
    extern __shared__ char smem[];
    const int tid = threadIdx.x;
    const int wid = tid >> 5, lane = tid & 31;
    const int m0 = blockIdx.y * 128, n0 = blockIdx.x * 128;
    const int wr = wid >> 2, wc = wid & 3;

    const __nv_bfloat16* gsrc0 = Ah + (size_t)m0 * GK;
    const __nv_bfloat16* gsrc1 = Al + (size_t)m0 * GK;
    const __nv_bfloat16* gsrc2 = Bh + (size_t)n0 * GK;
    const __nv_bfloat16* gsrc3 = Bl + (size_t)n0 * GK;

    float acc[4][4][4] = {};

    auto load_stage = [&](int c, int st) {
        const int k0 = c * KC;
        char* dstb = smem + st * STAGE_BYTES;
        #pragma unroll
        for (int i = 0; i < 8; i++) {
            int idx = tid + i * 256;
            int mat = idx >> 9;
            int row = (idx >> 2) & 127;
            int c16 = idx & 3;
            uint32_t dst = smem_u32(dstb + mat * MAT_BYTES + row * 80 + c16 * 16);
            const __nv_bfloat16* g =
                (mat == 0) ? gsrc0 : (mat == 1) ? gsrc1 : (mat == 2) ? gsrc2 : gsrc3;
            cpa16(dst, g + (size_t)row * GK + k0 + c16 * 8);
        }
        asm volatile("cp.async.commit_group;" ::: "memory");
    };

    load_stage(0, 0);

    for (int c = 0; c < NCH; c++) {
        if (c + 1 < NCH) {
            load_stage(c + 1, (c + 1) & 1);
            asm volatile("cp.async.wait_group 1;" ::: "memory");
        } else {
            asm volatile("cp.async.wait_group 0;" ::: "memory");
        }
        __syncthreads();

        const int st = c & 1;
        const uint32_t aH = smem_u32(smem + st * STAGE_BYTES);
        const uint32_t aL = aH + MAT_BYTES;
        const uint32_t bH = aH + 2 * MAT_BYTES;
        const uint32_t bL = aH + 3 * MAT_BYTES;

        #pragma unroll
        for (int kt = 0; kt < 2; kt++) {
            uint32_t ah[4][4], al[4][4], bh[2][4], bl[2][4];
            const int arow = wr * 64 + (lane & 15);
            const uint32_t akoff = (uint32_t)(kt * 16 + (lane >> 4) * 8) * 2;
            #pragma unroll
            for (int mt = 0; mt < 4; mt++) {
                ldsm4(ah[mt], aH + (uint32_t)(arow + mt * 16) * 80 + akoff);
                ldsm4(al[mt], aL + (uint32_t)(arow + mt * 16) * 80 + akoff);
            }
            const int g = lane >> 3;
            const int brow = wc * 32 + (lane & 7) + (g >> 1) * 8;
            const uint32_t bkoff = (uint32_t)(kt * 16 + (g & 1) * 8) * 2;
            #pragma unroll
            for (int nt2 = 0; nt2 < 2; nt2++) {
                ldsm4(bh[nt2], bH + (uint32_t)(brow + nt2 * 16) * 80 + bkoff);
                ldsm4(bl[nt2], bL + (uint32_t)(brow + nt2 * 16) * 80 + bkoff);
            }
            #pragma unroll
            for (int mt = 0; mt < 4; mt++)
                #pragma unroll
                for (int nt = 0; nt < 4; nt++) {
                    const uint32_t* bhp = &bh[nt >> 1][(nt & 1) * 2];
                    const uint32_t* blp = &bl[nt >> 1][(nt & 1) * 2];
                    mma16816(acc[mt][nt], ah[mt], bhp);
                    mma16816(acc[mt][nt], ah[mt], blp);
                    mma16816(acc[mt][nt], al[mt], bhp);
                }
        }
        __syncthreads();
    }

    const int qr = lane >> 2, qc = lane & 3;
    #pragma unroll
    for (int mt = 0; mt < 4; mt++) {
        #pragma unroll
        for (int nt = 0; nt < 4; nt++) {
            int row = m0 + wr * 64 + mt * 16 + qr;
            int col = n0 + wc * 32 + nt * 8 + qc * 2;
            if (Cf) {
                float bx = 0.f, by = 0.f;
                if (bias) { bx = bias[col]; by = bias[col + 1]; }
                float2 v0 = {acc[mt][nt][0] + bx, acc[mt][nt][1] + by};
                float2 v1 = {acc[mt][nt][2] + bx, acc[mt][nt][3] + by};
                *(float2*)&Cf[(size_t)row * GN + col] = v0;
                *(float2*)&Cf[(size_t)(row + 8) * GN + col] = v1;
            } else {
                #pragma unroll
                for (int hf = 0; hf < 2; hf++) {
                    int r = row + hf * 8;
                    __nv_bfloat16 h0, l0, h1, l1;
                    split2(acc[mt][nt][hf * 2 + 0], h0, l0);
                    split2(acc[mt][nt][hf * 2 + 1], h1, l1);
                    *(__nv_bfloat162*)&Ch[(size_t)r * GN + col] = __nv_bfloat162{h0, h1};
                    *(__nv_bfloat162*)&Cl[(size_t)r * GN + col] = __nv_bfloat162{l0, l1};
                }
            }
        }
    }
}

// ---------------- fp32 -> bf16 hi/lo split (x only) --------------------------
__global__ __launch_bounds__(256) void split_kernel(
    const float* __restrict__ in, __nv_bfloat16* __restrict__ hi,
    __nv_bfloat16* __restrict__ lo, int n4)
{
    int i = blockIdx.x * blockDim.x + threadIdx.x;
    if (i >= n4) return;
    float4 v = ((const float4*)in)[i];
    float vv[4] = {v.x, v.y, v.z, v.w};
    __nv_bfloat16 h[4], l[4];
    #pragma unroll
    for (int j = 0; j < 4; j++) split2(vv[j], h[j], l[j]);
    ((__nv_bfloat162*)hi)[2*i+0] = __nv_bfloat162{h[0], h[1]};
    ((__nv_bfloat162*)hi)[2*i+1] = __nv_bfloat162{h[2], h[3]};
    ((__nv_bfloat162*)lo)[2*i+0] = __nv_bfloat162{l[0], l[1]};
    ((__nv_bfloat162*)lo)[2*i+1] = __nv_bfloat162{l[2], l[3]};
}

// ---------------- transpose + split weights: W[K][N] -> Wt hi/lo [N][K] -----
__global__ void wsplit_t(const float* __restrict__ W,
                         __nv_bfloat16* __restrict__ th,
                         __nv_bfloat16* __restrict__ tl)
{
    __shared__ float t[32][33];
    const int k0 = blockIdx.y * 32, n0 = blockIdx.x * 32;
    for (int i = threadIdx.y; i < 32; i += 8)
        t[i][threadIdx.x] = W[(size_t)(k0 + i) * GN + n0 + threadIdx.x];
    __syncthreads();
    for (int i = threadIdx.y; i < 32; i += 8) {
        float v = t[threadIdx.x][i];
        __nv_bfloat16 h, l;
        split2(v, h, l);
        size_t o = (size_t)(n0 + i) * GK + k0 + threadIdx.x;
        th[o] = h;
        tl[o] = l;
    }
}

// ---------------- proj split (padded to 320 rows, zero fill) -----------------
__global__ void psplit(const float* __restrict__ proj)
{
    int i = blockIdx.x * 256 + threadIdx.x;
    if (i >= 320 * 64) return;
    int r = i >> 6, d = i & 63;
    float v = (r < RR) ? proj[r * 64 + d] : 0.0f;
    __nv_bfloat16 h, l;
    split2(v, h, l);
    g_projh[i] = h;
    g_projl[i] = l;
}

// ---------------- featmap HMMA: qp/kp = relu(head @ proj^T)+eps, h/l out -----
// grid (5, 32, 128), 256 threads, dyn smem FM_SMEM
__global__ __launch_bounds__(256) void featmap_hmma()
{
    extern __shared__ char smem[];
    const int tid = threadIdx.x, wid = tid >> 5, lane = tid & 31;
    const int r0 = blockIdx.x * 64;
    const int n0 = blockIdx.y * 128;
    const int z = blockIdx.z;
    const int which = z >> 6, bh = z & 63;
    const int b = bh >> 4, h = bh & 15;
    const __nv_bfloat16* __restrict__ Ahg = which ? g_kh : g_qh;
    const __nv_bfloat16* __restrict__ Alg = which ? g_kl : g_ql;
    __nv_bfloat16* __restrict__ dsth = which ? g_kph : g_qph;
    __nv_bfloat16* __restrict__ dstl = which ? g_kpl : g_qpl;
    const size_t abase = ((size_t)(b * NN + n0)) * GK + h * 64;

    const uint32_t sA_h = smem_u32(smem);
    const uint32_t sA_l = sA_h + 128 * 144;
    const uint32_t sB_h = sA_h + 2 * 128 * 144;
    const uint32_t sB_l = sB_h + 64 * 144;

    #pragma unroll
    for (int i = 0; i < 12; i++) {
        int idx = tid + i * 256;
        if (idx < 1024) {
            int row = idx >> 3, c = idx & 7;
            cpa16(sA_h + row * 144 + c * 16, Ahg + abase + (size_t)row * GK + c * 8);
        } else if (idx < 2048) {
            int j = idx - 1024; int row = j >> 3, c = j & 7;
            cpa16(sA_l + row * 144 + c * 16, Alg + abase + (size_t)row * GK + c * 8);
        } else if (idx < 2560) {
            int j = idx - 2048; int row = j >> 3, c = j & 7;
            cpa16(sB_h + row * 144 + c * 16, g_projh + (r0 + row) * 64 + c * 8);
        } else {
            int j = idx - 2560; int row = j >> 3, c = j & 7;
            cpa16(sB_l + row * 144 + c * 16, g_projl + (r0 + row) * 64 + c * 8);
        }
    }
    asm volatile("cp.async.commit_group;" ::: "memory");
    asm volatile("cp.async.wait_group 0;" ::: "memory");
    __syncthreads();

    const int wr = wid >> 2, wc = wid & 3;
    float acc[4][2][4] = {};

    #pragma unroll
    for (int kt = 0; kt < 4; kt++) {
        uint32_t ah[4][4], al[4][4], bh1[4], bl1[4];
        const int arow = wr * 64 + (lane & 15);
        const uint32_t ak = (uint32_t)(kt * 16 + (lane >> 4) * 8) * 2;
        #pragma unroll
        for (int mt = 0; mt < 4; mt++) {
            ldsm4(ah[mt], sA_h + (uint32_t)(arow + mt * 16) * 144 + ak);
            ldsm4(al[mt], sA_l + (uint32_t)(arow + mt * 16) * 144 + ak);
        }
        const int g = lane >> 3;
        const int brow = wc * 16 + (lane & 7) + (g >> 1) * 8;
        const uint32_t bk = (uint32_t)(kt * 16 + (g & 1) * 8) * 2;
        ldsm4(bh1, sB_h + (uint32_t)brow * 144 + bk);
        ldsm4(bl1, sB_l + (uint32_t)brow * 144 + bk);
        #pragma unroll
        for (int mt = 0; mt < 4; mt++)
            #pragma unroll
            for (int nt = 0; nt < 2; nt++) {
                mma16816(acc[mt][nt], ah[mt], &bh1[nt * 2]);
                mma16816(acc[mt][nt], ah[mt], &bl1[nt * 2]);
                mma16816(acc[mt][nt], al[mt], &bh1[nt * 2]);
            }
    }

    const int qr = lane >> 2, qc = lane & 3;
    #pragma unroll
    for (int mt = 0; mt < 4; mt++)
        #pragma unroll
        for (int nt = 0; nt < 2; nt++) {
            int r = r0 + wc * 16 + nt * 8 + qc * 2;
            if (r >= RP) continue;
            bool valid = (r < RR);   // 266 even -> pair-uniform
            #pragma unroll
            for (int hf = 0; hf < 2; hf++) {
                int nrow = n0 + wr * 64 + mt * 16 + qr + hf * 8;
                float v0 = acc[mt][nt][hf * 2 + 0];
                float v1 = acc[mt][nt][hf * 2 + 1];
                v0 = valid ? (fmaxf(v0, 0.0f) + EPSF) : 0.0f;
                v1 = valid ? (fmaxf(v1, 0.0f) + EPSF) : 0.0f;
                __nv_bfloat16 h0, l0, h1, l1;
                split2(v0, h0, l0);
                split2(v1, h1, l1);
                size_t o = ((size_t)bh * NN + nrow) * RP + r;
                *(__nv_bfloat162*)&dsth[o] = __nv_bfloat162{h0, h1};
                *(__nv_bfloat162*)&dstl[o] = __nv_bfloat162{l0, l1};
            }
        }
}

// ---------------- k_sum = sum_n kp -------------------------------------------
__global__ void ksum_kernel()
{
    const int bh = blockIdx.x;
    const int r = blockIdx.y * 128 + threadIdx.x;
    if (r >= RR) return;
    const int n0 = blockIdx.z * 256;
    const __nv_bfloat16* __restrict__ bh_ = g_kph + (size_t)bh * NN * RP;
    const __nv_bfloat16* __restrict__ bl_ = g_kpl + (size_t)bh * NN * RP;
    float s = 0.f;
    #pragma unroll 4
    for (int n = n0; n < n0 + 256; n++) {
        size_t o = (size_t)n * RP + r;
        s += __bfloat162float(bh_[o]) + __bfloat162float(bl_[o]);
    }
    atomicAdd(&g_ksum[bh * RP + r], s);
}

// ---------------- d_inv = 1 / (qp . k_sum) -----------------------------------
__global__ void dinv_kernel()
{
    const int gw = (blockIdx.x * blockDim.x + threadIdx.x) >> 5;
    const int lane = threadIdx.x & 31;
    const int bh = gw >> 12;
    const int n = gw & 4095;
    const __nv_bfloat16* __restrict__ qh_ = g_qph + ((size_t)bh * NN + n) * RP;
    const __nv_bfloat16* __restrict__ ql_ = g_qpl + ((size_t)bh * NN + n) * RP;
    const float* __restrict__ ks = g_ksum + bh * RP;
    float s = 0.f;
    for (int r = lane; r < RR; r += 32)
        s += (__bfloat162float(qh_[r]) + __bfloat162float(ql_[r])) * ks[r];
    #pragma unroll
    for (int o = 16; o; o >>= 1) s += __shfl_xor_sync(0xffffffffu, s, o);
    if (lane == 0) g_dinv[(size_t)bh * NN + n] = 1.0f / s;
}

// ---------------- kv = kp^T @ v per head; writes kvT[d][r] h/l ---------------
__global__ __launch_bounds__(256) void kv_kernel()
{
    const int bh = blockIdx.x;
    const int b = bh >> 4, h = bh & 15;
    const int r0 = blockIdx.y * 64;

    __shared__ float kps[64][65];
    __shared__ float vs[64][64];
    const int tid = threadIdx.x;
    const int rlo = tid >> 3;
    const int c0 = (tid & 7) * 8;

    float acc0[8] = {}, acc1[8] = {};
    const __nv_bfloat16* __restrict__ kph_ = g_kph + (size_t)bh * NN * RP;
    const __nv_bfloat16* __restrict__ kpl_ = g_kpl + (size_t)bh * NN * RP;
    const float* __restrict__ vb = g_v + (size_t)b * NN * CC + h * 64;

    for (int n0 = 0; n0 < NN; n0 += 64) {
        #pragma unroll
        for (int t = 0; t < 16; t++) {
            int e = tid + t * 256;
            int nn = e >> 6, rl = e & 63;
            int rr = r0 + rl;
            float val = 0.f;
            if (rr < RP) {
                size_t o = (size_t)(n0 + nn) * RP + rr;
                val = __bfloat162float(kph_[o]) + __bfloat162float(kpl_[o]);
            }
            kps[nn][rl] = val;
        }
        #pragma unroll
        for (int t = 0; t < 16; t++) {
            int e = tid + t * 256;
            int nn = e >> 6, c = e & 63;
            vs[nn][c] = vb[(size_t)(n0 + nn) * CC + c];
        }
        __syncthreads();
        #pragma unroll 8
        for (int nn = 0; nn < 64; nn++) {
            float a0 = kps[nn][rlo];
            float a1 = kps[nn][rlo + 32];
            float4 v0 = *(const float4*)&vs[nn][c0];
            float4 v1 = *(const float4*)&vs[nn][c0 + 4];
            acc0[0] += a0 * v0.x; acc0[1] += a0 * v0.y;
            acc0[2] += a0 * v0.z; acc0[3] += a0 * v0.w;
            acc0[4] += a0 * v1.x; acc0[5] += a0 * v1.y;
            acc0[6] += a0 * v1.z; acc0[7] += a0 * v1.w;
            acc1[0] += a1 * v0.x; acc1[1] += a1 * v0.y;
            acc1[2] += a1 * v0.z; acc1[3] += a1 * v0.w;
            acc1[4] += a1 * v1.x; acc1[5] += a1 * v1.y;
            acc1[6] += a1 * v1.z; acc1[7] += a1 * v1.w;
        }
        __syncthreads();
    }

    int rr0 = r0 + rlo, rr1 = rr0 + 32;
    if (rr0 < RR) {
        #pragma unroll
        for (int j = 0; j < 8; j++) {
            __nv_bfloat16 hh, ll;
            split2(acc0[j], hh, ll);
            size_t o = ((size_t)bh * 64 + c0 + j) * RP + rr0;
            g_kvTh[o] = hh; g_kvTl[o] = ll;
        }
    }
    if (rr1 < RR) {
        #pragma unroll
        for (int j = 0; j < 8; j++) {
            __nv_bfloat16 hh, ll;
            split2(acc1[j], hh, ll);
            size_t o = ((size_t)bh * 64 + c0 + j) * RP + rr1;
            g_kvTh[o] = hh; g_kvTl[o] = ll;
        }
    }
}

// ---------------- qkv HMMA: om = (qp @ kvT^T) * d_inv, h/l out ---------------
// grid (32, 64), 256 threads, dyn smem QKV_SMEM
__global__ __launch_bounds__(256) void qkv_hmma()
{
    extern __shared__ char smem[];
    const int tid = threadIdx.x, wid = tid >> 5, lane = tid & 31;
    const int n0 = blockIdx.x * 128;
    const int bh = blockIdx.y;
    const int b = bh >> 4, h = bh & 15;

    const __nv_bfloat16* __restrict__ Ahg = g_qph + ((size_t)bh * NN + n0) * RP;
    const __nv_bfloat16* __restrict__ Alg = g_qpl + ((size_t)bh * NN + n0) * RP;
    const __nv_bfloat16* __restrict__ Bhg = g_kvTh + (size_t)bh * 64 * RP;
    const __nv_bfloat16* __restrict__ Blg = g_kvTl + (size_t)bh * 64 * RP;

    float acc[4][2][4] = {};

    auto load_stage = [&](int c, int st) {
        const int k0 = c * KC;
        char* dstb = smem + st * QKV_STAGE;
        #pragma unroll
        for (int i = 0; i < 6; i++) {
            int idx = tid + i * 256;
            uint32_t dst;
            const __nv_bfloat16* src;
            if (idx < 512) {
                int row = idx >> 2, cc = idx & 3;
                dst = smem_u32(dstb + row * 80 + cc * 16);
                src = Ahg + (size_t)row * RP + k0 + cc * 8;
            } else if (idx < 1024) {
                int j = idx - 512; int row = j >> 2, cc = j & 3;
                dst = smem_u32(dstb + 128 * 80 + row * 80 + cc * 16);
                src = Alg + (size_t)row * RP + k0 + cc * 8;
            } else if (idx < 1280) {
                int j = idx - 1024; int row = j >> 2, cc = j & 3;
                dst = smem_u32(dstb + 2 * 128 * 80 + row * 80 + cc * 16);
                src = Bhg + (size_t)row * RP + k0 + cc * 8;
            } else {
                int j = idx - 1280; int row = j >> 2, cc = j & 3;
                dst = smem_u32(dstb + 2 * 128 * 80 + 64 * 80 + row * 80 + cc * 16);
                src = Blg + (size_t)row * RP + k0 + cc * 8;
            }
            cpa16(dst, src);
        }
        asm volatile("cp.async.commit_group;" ::: "memory");
    };

    const int NCH2 = RP / KC;  // 9
    load_stage(0, 0);

    for (int c = 0; c < NCH2; c++) {
        if (c + 1 < NCH2) {
            load_stage(c + 1, (c + 1) & 1);
            asm volatile("cp.async.wait_group 1;" ::: "memory");
        } else {
            asm volatile("cp.async.wait_group 0;" ::: "memory");
        }
        __syncthreads();

        const int st = c & 1;
        const uint32_t aH = smem_u32(smem + st * QKV_STAGE);
        const uint32_t aL = aH + 128 * 80;
        const uint32_t bH = aH + 2 * 128 * 80;
        const uint32_t bL = bH + 64 * 80;
        const int wr = wid >> 2, wc = wid & 3;

        #pragma unroll
        for (int kt = 0; kt < 2; kt++) {
            uint32_t ah[4][4], al[4][4], bh1[4], bl1[4];
            const int arow = wr * 64 + (lane & 15);
            const uint32_t ak = (uint32_t)(kt * 16 + (lane >> 4) * 8) * 2;
            #pragma unroll
            for (int mt = 0; mt < 4; mt++) {
                ldsm4(ah[mt], aH + (uint32_t)(arow + mt * 16) * 80 + ak);
                ldsm4(al[mt], aL + (uint32_t)(arow + mt * 16) * 80 + ak);
            }
            const int g = lane >> 3;
            const int brow = wc * 16 + (lane & 7) + (g >> 1) * 8;
            const uint32_t bk = (uint32_t)(kt * 16 + (g & 1) * 8) * 2;
            ldsm4(bh1, bH + (uint32_t)brow * 80 + bk);
            ldsm4(bl1, bL + (uint32_t)brow * 80 + bk);
            #pragma unroll
            for (int mt = 0; mt < 4; mt++)
                #pragma unroll
                for (int nt = 0; nt < 2; nt++) {
                    mma16816(acc[mt][nt], ah[mt], &bh1[nt * 2]);
                    mma16816(acc[mt][nt], ah[mt], &bl1[nt * 2]);
                    mma16816(acc[mt][nt], al[mt], &bh1[nt * 2]);
                }
        }
        __syncthreads();
    }

    const int wr = wid >> 2, wc = wid & 3;
    const int qr = lane >> 2, qc = lane & 3;
    #pragma unroll
    for (int mt = 0; mt < 4; mt++)
        #pragma unroll
        for (int nt = 0; nt < 2; nt++) {
            int d = wc * 16 + nt * 8 + qc * 2;
            #pragma unroll
            for (int hf = 0; hf < 2; hf++) {
                int nrow = n0 + wr * 64 + mt * 16 + qr + hf * 8;
                float di = g_dinv[(size_t)bh * NN + nrow];
                float v0 = acc[mt][nt][hf * 2 + 0] * di;
                float v1 = acc[mt][nt][hf * 2 + 1] * di;
                __nv_bfloat16 h0, l0, h1, l1;
                split2(v0, h0, l0);
                split2(v1, h1, l1);
                size_t o = ((size_t)(b * NN + nrow)) * GK + h * 64 + d;
                *(__nv_bfloat162*)&g_omh[o] = __nv_bfloat162{h0, h1};
                *(__nv_bfloat162*)&g_oml[o] = __nv_bfloat162{l0, l1};
            }
        }
}

// ---------------- launch -----------------------------------------------------
extern "C" void kernel_launch(void* const* d_in, const int* in_sizes, int n_in,
                              void* d_out, int out_size)
{
    const float* x    = (const float*)d_in[0];
    const float* Wq   = (const float*)d_in[1];
    const float* Wk   = (const float*)d_in[2];
    const float* Wv   = (const float*)d_in[3];
    const float* Wo   = (const float*)d_in[4];
    const float* bo   = (const float*)d_in[5];
    const float* proj = (const float*)d_in[6];

    float *v, *ksum;
    __nv_bfloat16 *xh, *xl, *qh, *ql, *kh, *kl, *omh, *oml, *wth, *wtl, *kvth, *kvtl;
    cudaGetSymbolAddress((void**)&v,    g_v);
    cudaGetSymbolAddress((void**)&ksum, g_ksum);
    cudaGetSymbolAddress((void**)&xh,   g_xh);
    cudaGetSymbolAddress((void**)&xl,   g_xl);
    cudaGetSymbolAddress((void**)&qh,   g_qh);
    cudaGetSymbolAddress((void**)&ql,   g_ql);
    cudaGetSymbolAddress((void**)&kh,   g_kh);
    cudaGetSymbolAddress((void**)&kl,   g_kl);
    cudaGetSymbolAddress((void**)&omh,  g_omh);
    cudaGetSymbolAddress((void**)&oml,  g_oml);
    cudaGetSymbolAddress((void**)&wth,  g_wth);
    cudaGetSymbolAddress((void**)&wtl,  g_wtl);
    cudaGetSymbolAddress((void**)&kvth, g_kvTh);
    cudaGetSymbolAddress((void**)&kvtl, g_kvTl);

    cudaFuncSetAttribute(gemm_hmma,
                         cudaFuncAttributeMaxDynamicSharedMemorySize, SMEM_DYN);
    cudaFuncSetAttribute(featmap_hmma,
                         cudaFuncAttributeMaxDynamicSharedMemorySize, FM_SMEM);
    cudaFuncSetAttribute(qkv_hmma,
                         cudaFuncAttributeMaxDynamicSharedMemorySize, QKV_SMEM);

    const int n4 = GM * GK / 4;

    split_kernel<<<(n4 + 255) / 256, 256>>>(x, xh, xl, n4);
    wsplit_t<<<dim3(32, 32), dim3(32, 8)>>>(Wq, wth + 0 * (size_t)GN * GK, wtl + 0 * (size_t)GN * GK);
    wsplit_t<<<dim3(32, 32), dim3(32, 8)>>>(Wk, wth + 1 * (size_t)GN * GK, wtl + 1 * (size_t)GN * GK);
    wsplit_t<<<dim3(32, 32), dim3(32, 8)>>>(Wv, wth + 2 * (size_t)GN * GK, wtl + 2 * (size_t)GN * GK);
    wsplit_t<<<dim3(32, 32), dim3(32, 8)>>>(Wo, wth + 3 * (size_t)GN * GK, wtl + 3 * (size_t)GN * GK);
    psplit<<<80, 256>>>(proj);

    dim3 gG(GN / 128, GM / 128);
    gemm_hmma<<<gG, 256, SMEM_DYN>>>(xh, xl, wth + 0 * (size_t)GN * GK, wtl + 0 * (size_t)GN * GK,
                                     nullptr, nullptr, qh, ql);
    gemm_hmma<<<gG, 256, SMEM_DYN>>>(xh, xl, wth + 1 * (size_t)GN * GK, wtl + 1 * (size_t)GN * GK,
                                     nullptr, nullptr, kh, kl);
    gemm_hmma<<<gG, 256, SMEM_DYN>>>(xh, xl, wth + 2 * (size_t)GN * GK, wtl + 2 * (size_t)GN * GK,
                                     nullptr, v, nullptr, nullptr);

    featmap_hmma<<<dim3(5, 32, 128), 256, FM_SMEM>>>();

    cudaMemsetAsync(ksum, 0, BHN * RP * sizeof(float));
    ksum_kernel<<<dim3(BHN, 3, NN / 256), 128>>>();

    dinv_kernel<<<(BHN * NN) / 8, 256>>>();

    cudaMemsetAsync(kvth, 0, BHN * 64 * RP * sizeof(__nv_bfloat16));
    cudaMemsetAsync(kvtl, 0, BHN * 64 * RP * sizeof(__nv_bfloat16));
    kv_kernel<<<dim3(BHN, 5), 256>>>();

    qkv_hmma<<<dim3(32, BHN), 256, QKV_SMEM>>>();

    gemm_hmma<<<gG, 256, SMEM_DYN>>>(omh, oml, wth + 3 * (size_t)GN * GK, wtl + 3 * (size_t)GN * GK,
                                     bo, (float*)d_out, nullptr, nullptr);
}